// round 2
// baseline (speedup 1.0000x reference)
#include <cuda_runtime.h>
#include <cstdint>
#include <cstdio>

#define BB 8
#define HH 128
#define WW 256
#define CC 128
#define NP (BB*HH*WW)        // 262144 pixels
#define CIN1P 144            // layer-1 input channels padded 134 -> 144 (mult of 16)

// ---------------- scratch (device globals; no allocations allowed) ----------------
__device__ float g_vol [(size_t)NP * CIN1P];   // padded 144-ch input volume
__device__ float g_bufA[(size_t)NP * 128];
__device__ float g_bufB[(size_t)NP * 128];
__device__ float g_up  [NP];
__device__ float g_warp[NP];
__device__ float g_lm  [NP];
__device__ float g_w1  [9 * CIN1P * 128];      // zero-padded layer-1 weights

// ---------------- prologue: upsample + warp + leftmean ----------------
__global__ void prep_kernel(const float* __restrict__ left,
                            const float* __restrict__ right,
                            const float* __restrict__ pd)
{
    int p = blockIdx.x * 256 + threadIdx.x;
    int b = p >> 15;
    int h = (p >> 8) & 127;
    int w = p & 255;

    // --- bilinear 2x upsample (half-pixel, edge-renorm == clamp) ---
    float sy = h * 0.5f - 0.25f;
    float fy = floorf(sy); float ty = sy - fy; int iy = (int)fy;
    int y0 = min(max(iy, 0), 63), y1 = min(max(iy + 1, 0), 63);
    float sx = w * 0.5f - 0.25f;
    float fx = floorf(sx); float tx = sx - fx; int ix = (int)fx;
    int x0 = min(max(ix, 0), 127), x1 = min(max(ix + 1, 0), 127);
    const float* q = pd + b * (64 * 128);
    float v00 = q[y0 * 128 + x0], v01 = q[y0 * 128 + x1];
    float v10 = q[y1 * 128 + x0], v11 = q[y1 * 128 + x1];
    float up = (1.f - ty) * ((1.f - tx) * v00 + tx * v01)
             + ty        * ((1.f - tx) * v10 + tx * v11);
    g_up[p] = up;

    // --- warp (reference semantics: pixel-flat gather from right.reshape(-1)) ---
    // cy = h exactly -> wt_y1 == 0, only the y0 row contributes.
    float cx  = (float)w - up;
    float xf  = floorf(cx);
    float wt0 = (xf + 1.0f) - cx;
    float wt1 = cx - xf;
    float x0s = fminf(fmaxf(xf,       0.f), 255.f);
    float x1s = fminf(fmaxf(xf + 1.f, 0.f), 255.f);
    float basef = (float)(b * 32768) + (float)(h * 256);
    int i0 = (int)(x0s + basef);
    int i1 = (int)(x1s + basef);
    g_warp[p] = wt0 * right[i0] + wt1 * right[i1];

    // --- channel mean of left ---
    const float4* lp = (const float4*)(left + (size_t)p * CC);
    float s = 0.f;
    #pragma unroll
    for (int q4 = 0; q4 < 32; q4++) { float4 v = lp[q4]; s += v.x + v.y + v.z + v.w; }
    g_lm[p] = s * (1.0f / 128.0f);
}

// ---------------- build padded 144-ch volume ----------------
__global__ void buildvol_kernel(const float* __restrict__ left)
{
    int p = blockIdx.x * 256 + threadIdx.x;
    float4* dst = (float4*)(g_vol + (size_t)p * CIN1P);
    const float4* src = (const float4*)(left + (size_t)p * CC);
    #pragma unroll
    for (int q = 0; q < 32; q++) dst[q] = src[q];

    float lm = g_lm[p];
    int w = p & 255;
    int prow = p & ~255;
    float c[8];
    #pragma unroll
    for (int i = 0; i < 5; i++) {
        int ws = w + i - 2;
        c[i] = ((unsigned)ws < 256u) ? lm * g_warp[prow + ws] : 0.f;
    }
    c[5] = g_up[p]; c[6] = 0.f; c[7] = 0.f;
    float* d = g_vol + (size_t)p * CIN1P + 128;
    #pragma unroll
    for (int i = 0; i < 8; i++) d[i] = c[i];
    #pragma unroll
    for (int i = 8; i < 16; i++) d[i] = 0.f;
}

// ---------------- zero-pad layer-1 weights [3,3,134,128] -> [9,144,128] ----------------
__global__ void padw1_kernel(const float* __restrict__ k1)
{
    int idx = blockIdx.x * 256 + threadIdx.x;
    if (idx >= 9 * CIN1P * 128) return;
    int n   = idx & 127;
    int rc  = idx >> 7;
    int c   = rc % CIN1P;
    int pos = rc / CIN1P;
    g_w1[idx] = (c < 134) ? k1[(pos * 134 + c) * 128 + n] : 0.f;
}

// ---------------- 3x3 SAME conv, NHWC, implicit-GEMM with raw-tile staging ----------------
// Block: BM=128 pixels (one contiguous w-run in one row) x BN=COUT channels.
// Per-thread: TM=8 x TN register tile. 256 threads. Channel chunks of BK=16.
template<int CIN, int COUT, int TN, bool LRELU>
__global__ __launch_bounds__(256, 2)
void conv3x3_kernel(const float* __restrict__ in, const float* __restrict__ wg,
                    const float* __restrict__ bias, float* __restrict__ out)
{
    constexpr int BM = 128, TM = 8, BK = 16, BN = COUT;
    __shared__ float sIn[BK * 3 * 132];   // [k][row][x], x in [0,130), padded
    __shared__ float sW [BK * BN];        // [k][n]

    const int tid = threadIdx.x;
    const int tx  = tid & 15;
    const int ty  = tid >> 4;
    const int p0  = blockIdx.x * BM;
    const int b   = p0 >> 15;
    const int h   = (p0 >> 8) & 127;
    const int w0  = p0 & 255;

    const float* inb = in + (size_t)(b * HH) * WW * CIN;

    float acc[TM][TN];
    #pragma unroll
    for (int i = 0; i < TM; i++)
        #pragma unroll
        for (int j = 0; j < TN; j++) acc[i][j] = 0.f;

    #pragma unroll 1
    for (int c0 = 0; c0 < CIN; c0 += BK) {
        __syncthreads();
        // stage raw input tile: 3 rows x 130 cols x 16 channels
        #pragma unroll 1
        for (int idx = tid; idx < 3 * 130 * 4; idx += 256) {
            int c4 = idx & 3;
            int x  = (idx >> 2) % 130;
            int r  = (idx >> 2) / 130;
            int hh = h + r - 1;
            int ww = w0 + x - 1;
            float4 v = make_float4(0.f, 0.f, 0.f, 0.f);
            if ((unsigned)hh < (unsigned)HH && (unsigned)ww < (unsigned)WW)
                v = *(const float4*)(inb + ((size_t)hh * WW + ww) * CIN + (c0 + c4 * 4));
            float* s = sIn + r * 132 + x;
            s[(c4 * 4 + 0) * 396] = v.x;
            s[(c4 * 4 + 1) * 396] = v.y;
            s[(c4 * 4 + 2) * 396] = v.z;
            s[(c4 * 4 + 3) * 396] = v.w;
        }
        int ky = 0, kx = 0;
        #pragma unroll 1
        for (int pos = 0; pos < 9; pos++) {
            __syncthreads();
            // stage weight chunk [BK][BN] (HWIO is already k-major x n-contiguous)
            const float* wp = wg + ((size_t)pos * CIN + c0) * COUT;
            #pragma unroll 1
            for (int idx = tid; idx < BK * BN / 4; idx += 256) {
                int n4 = idx % (BN / 4);
                int k  = idx / (BN / 4);
                *(float4*)&sW[k * BN + n4 * 4] = *(const float4*)(wp + k * COUT + n4 * 4);
            }
            __syncthreads();

            const float* aRow = sIn + ky * 132 + (ty * TM + kx);
            #pragma unroll 4
            for (int k = 0; k < BK; k++) {
                float a[TM];
                #pragma unroll
                for (int i = 0; i < TM; i++) a[i] = aRow[k * 396 + i];
                float bb[TN];
                if constexpr (TN % 4 == 0) {
                    #pragma unroll
                    for (int j4 = 0; j4 < TN / 4; j4++) {
                        float4 v = *(const float4*)&sW[k * BN + tx * TN + j4 * 4];
                        bb[j4 * 4 + 0] = v.x; bb[j4 * 4 + 1] = v.y;
                        bb[j4 * 4 + 2] = v.z; bb[j4 * 4 + 3] = v.w;
                    }
                } else if constexpr (TN % 2 == 0) {
                    #pragma unroll
                    for (int j2 = 0; j2 < TN / 2; j2++) {
                        float2 v = *(const float2*)&sW[k * BN + tx * TN + j2 * 2];
                        bb[j2 * 2 + 0] = v.x; bb[j2 * 2 + 1] = v.y;
                    }
                } else {
                    #pragma unroll
                    for (int j = 0; j < TN; j++) bb[j] = sW[k * BN + tx * TN + j];
                }
                #pragma unroll
                for (int i = 0; i < TM; i++)
                    #pragma unroll
                    for (int j = 0; j < TN; j++)
                        acc[i][j] = fmaf(a[i], bb[j], acc[i][j]);
            }
            kx++; if (kx == 3) { kx = 0; ky++; }
        }
    }

    // epilogue: bias + optional leaky relu
    #pragma unroll
    for (int i = 0; i < TM; i++) {
        int p = p0 + ty * TM + i;
        float* op = out + (size_t)p * COUT + tx * TN;
        #pragma unroll
        for (int j = 0; j < TN; j++) {
            float v = acc[i][j] + bias[tx * TN + j];
            if (LRELU) v = (v >= 0.f) ? v : 0.2f * v;
            op[j] = v;
        }
    }
}

// ---------------- final 32 -> 1 conv (linear head) ----------------
__global__ void conv_last_kernel(const float* __restrict__ in, const float* __restrict__ k6,
                                 const float* __restrict__ b6, float* __restrict__ out)
{
    __shared__ float sw[288];
    int tid = threadIdx.x;
    for (int i = tid; i < 288; i += 256) sw[i] = k6[i];   // FIX: was `if (tid < 288)` with 256 threads
    __syncthreads();

    int p = blockIdx.x * 256 + tid;
    int b = p >> 15, h = (p >> 8) & 127, w = p & 255;
    const float* inb = in + (size_t)(b * HH) * WW * 32;
    float acc = b6[0];
    #pragma unroll
    for (int ky = 0; ky < 3; ky++) {
        int hh = h + ky - 1;
        if ((unsigned)hh >= 128u) continue;
        #pragma unroll
        for (int kx = 0; kx < 3; kx++) {
            int ww = w + kx - 1;
            if ((unsigned)ww >= 256u) continue;
            const float4* ip = (const float4*)(inb + ((size_t)hh * 256 + ww) * 32);
            const float* wv = &sw[(ky * 3 + kx) * 32];
            #pragma unroll
            for (int q = 0; q < 8; q++) {
                float4 v = ip[q];
                acc += v.x * wv[4 * q + 0] + v.y * wv[4 * q + 1]
                     + v.z * wv[4 * q + 2] + v.w * wv[4 * q + 3];
            }
        }
    }
    out[p] = acc;
}

// ---------------- launch ----------------
extern "C" void kernel_launch(void* const* d_in, const int* in_sizes, int n_in,
                              void* d_out, int out_size)
{
    (void)in_sizes; (void)n_in; (void)out_size;
    const float* left  = (const float*)d_in[0];
    const float* right = (const float*)d_in[1];
    const float* pd    = (const float*)d_in[2];
    const float* k1 = (const float*)d_in[3];  const float* b1 = (const float*)d_in[4];
    const float* k2 = (const float*)d_in[5];  const float* b2 = (const float*)d_in[6];
    const float* k3 = (const float*)d_in[7];  const float* b3 = (const float*)d_in[8];
    const float* k4 = (const float*)d_in[9];  const float* b4 = (const float*)d_in[10];
    const float* k5 = (const float*)d_in[11]; const float* b5 = (const float*)d_in[12];
    const float* k6 = (const float*)d_in[13]; const float* b6 = (const float*)d_in[14];
    float* out = (float*)d_out;

    float *vol, *bufA, *bufB, *w1;
    cudaGetSymbolAddress((void**)&vol,  g_vol);
    cudaGetSymbolAddress((void**)&bufA, g_bufA);
    cudaGetSymbolAddress((void**)&bufB, g_bufB);
    cudaGetSymbolAddress((void**)&w1,   g_w1);

    prep_kernel    <<<NP / 256, 256>>>(left, right, pd);
    buildvol_kernel<<<NP / 256, 256>>>(left);
    padw1_kernel   <<<(9 * CIN1P * 128 + 255) / 256, 256>>>(k1);

    conv3x3_kernel<CIN1P, 128, 8, true><<<NP / 128, 256>>>(vol,  w1, b1, bufA);
    conv3x3_kernel<128,   128, 8, true><<<NP / 128, 256>>>(bufA, k2, b2, bufB);
    conv3x3_kernel<128,    96, 6, true><<<NP / 128, 256>>>(bufB, k3, b3, bufA);
    conv3x3_kernel<96,     64, 4, true><<<NP / 128, 256>>>(bufA, k4, b4, bufB);
    conv3x3_kernel<64,     32, 2, true><<<NP / 128, 256>>>(bufB, k5, b5, bufA);
    conv_last_kernel<<<NP / 256, 256>>>(bufA, k6, b6, out);
}

// round 3
// speedup vs baseline: 1.3733x; 1.3733x over previous
#include <cuda_runtime.h>
#include <cstdint>
#include <cstdio>

#define BB 8
#define HH 128
#define WW 256
#define CC 128
#define NP (BB*HH*WW)        // 262144 pixels
#define CIN1P 144            // layer-1 input channels padded 134 -> 144

typedef unsigned long long ull;

// ---------------- scratch (device globals; no allocations allowed) ----------------
__device__ float g_vol [(size_t)NP * CIN1P];
__device__ float g_bufA[(size_t)NP * 128];
__device__ float g_bufB[(size_t)NP * 128];
__device__ float g_up  [NP];
__device__ float g_warp[NP];
__device__ float g_lm  [NP];
__device__ float g_w1  [9 * CIN1P * 128];

// ---------------- packed f32x2 helpers ----------------
__device__ __forceinline__ void ffma2(ull& d, ull a, ull b) {
    asm("fma.rn.f32x2 %0, %1, %2, %0;" : "+l"(d) : "l"(a), "l"(b));
}
__device__ __forceinline__ ull pack2(float x) {
    ull r; asm("mov.b64 %0, {%1, %1};" : "=l"(r) : "f"(x)); return r;
}
__device__ __forceinline__ float2 unpack2(ull v) {
    float2 r; asm("mov.b64 {%0, %1}, %2;" : "=f"(r.x), "=f"(r.y) : "l"(v)); return r;
}

// ---------------- prologue: upsample + warp + leftmean ----------------
__global__ void prep_kernel(const float* __restrict__ left,
                            const float* __restrict__ right,
                            const float* __restrict__ pd)
{
    int p = blockIdx.x * 256 + threadIdx.x;
    int b = p >> 15;
    int h = (p >> 8) & 127;
    int w = p & 255;

    float sy = h * 0.5f - 0.25f;
    float fy = floorf(sy); float ty = sy - fy; int iy = (int)fy;
    int y0 = min(max(iy, 0), 63), y1 = min(max(iy + 1, 0), 63);
    float sx = w * 0.5f - 0.25f;
    float fx = floorf(sx); float tx = sx - fx; int ix = (int)fx;
    int x0 = min(max(ix, 0), 127), x1 = min(max(ix + 1, 0), 127);
    const float* q = pd + b * (64 * 128);
    float v00 = q[y0 * 128 + x0], v01 = q[y0 * 128 + x1];
    float v10 = q[y1 * 128 + x0], v11 = q[y1 * 128 + x1];
    float up = (1.f - ty) * ((1.f - tx) * v00 + tx * v01)
             + ty        * ((1.f - tx) * v10 + tx * v11);
    g_up[p] = up;

    float cx  = (float)w - up;
    float xf  = floorf(cx);
    float wt0 = (xf + 1.0f) - cx;
    float wt1 = cx - xf;
    float x0s = fminf(fmaxf(xf,       0.f), 255.f);
    float x1s = fminf(fmaxf(xf + 1.f, 0.f), 255.f);
    float basef = (float)(b * 32768) + (float)(h * 256);
    int i0 = (int)(x0s + basef);
    int i1 = (int)(x1s + basef);
    g_warp[p] = wt0 * right[i0] + wt1 * right[i1];

    const float4* lp = (const float4*)(left + (size_t)p * CC);
    float s = 0.f;
    #pragma unroll
    for (int q4 = 0; q4 < 32; q4++) { float4 v = lp[q4]; s += v.x + v.y + v.z + v.w; }
    g_lm[p] = s * (1.0f / 128.0f);
}

// ---------------- build padded 144-ch volume ----------------
__global__ void buildvol_kernel(const float* __restrict__ left)
{
    int p = blockIdx.x * 256 + threadIdx.x;
    float4* dst = (float4*)(g_vol + (size_t)p * CIN1P);
    const float4* src = (const float4*)(left + (size_t)p * CC);
    #pragma unroll
    for (int q = 0; q < 32; q++) dst[q] = src[q];

    float lm = g_lm[p];
    int w = p & 255;
    int prow = p & ~255;
    float c[8];
    #pragma unroll
    for (int i = 0; i < 5; i++) {
        int ws = w + i - 2;
        c[i] = ((unsigned)ws < 256u) ? lm * g_warp[prow + ws] : 0.f;
    }
    c[5] = g_up[p]; c[6] = 0.f; c[7] = 0.f;
    float* d = g_vol + (size_t)p * CIN1P + 128;
    #pragma unroll
    for (int i = 0; i < 8; i++) d[i] = c[i];
    #pragma unroll
    for (int i = 8; i < 16; i++) d[i] = 0.f;
}

// ---------------- zero-pad layer-1 weights ----------------
__global__ void padw1_kernel(const float* __restrict__ k1)
{
    int idx = blockIdx.x * 256 + threadIdx.x;
    if (idx >= 9 * CIN1P * 128) return;
    int n   = idx & 127;
    int rc  = idx >> 7;
    int c   = rc % CIN1P;
    int pos = rc / CIN1P;
    g_w1[idx] = (c < 134) ? k1[(pos * 134 + c) * 128 + n] : 0.f;
}

// ---------------- 3x3 conv v2: all-9-tap weight staging + FFMA2 + reg window ----------------
// Block: 128 pixels x COUT. 256 threads (tx=16 over channels, ty=16 over pixels).
// Per-thread: TM=8 pixels x TN channels (as TN/2 f32x2 pairs). BK=16 channel chunks.
template<int CIN, int COUT, int TN, bool LRELU>
__global__ __launch_bounds__(256, 2)
void conv3x3_v2(const float* __restrict__ in, const float* __restrict__ wg,
                const float* __restrict__ bias, float* __restrict__ out)
{
    constexpr int BM = 128, TM = 8, BK = 16, BN = COUT, S = 132;
    extern __shared__ float smem[];
    float* sIn = smem;                  // [BK][3][S]
    float* sW  = smem + BK * 3 * S;     // [9][BK][BN]

    const int tid = threadIdx.x;
    const int tx  = tid & 15;
    const int ty  = tid >> 4;
    const int p0  = blockIdx.x * BM;
    const int b   = p0 >> 15;
    const int h   = (p0 >> 8) & 127;
    const int w0  = p0 & 255;

    const float* inb = in + (size_t)(b * HH) * WW * CIN;

    ull acc[TM][TN / 2];
    #pragma unroll
    for (int i = 0; i < TM; i++)
        #pragma unroll
        for (int j = 0; j < TN / 2; j++) acc[i][j] = 0ull;

    #pragma unroll 1
    for (int c0 = 0; c0 < CIN; c0 += BK) {
        __syncthreads();
        // stage input tile: 3 rows x 130 cols x 16 channels, layout [k][r][x]
        #pragma unroll 1
        for (int idx = tid; idx < 3 * 130 * (BK / 4); idx += 256) {
            int c4 = idx & 3;
            int x  = (idx >> 2) % 130;
            int r  = (idx >> 2) / 130;
            int hh = h + r - 1;
            int ww = w0 + x - 1;
            float4 v = make_float4(0.f, 0.f, 0.f, 0.f);
            if ((unsigned)hh < (unsigned)HH && (unsigned)ww < (unsigned)WW)
                v = *(const float4*)(inb + ((size_t)hh * WW + ww) * CIN + (c0 + c4 * 4));
            float* s = sIn + r * S + x;
            s[(c4 * 4 + 0) * (3 * S)] = v.x;
            s[(c4 * 4 + 1) * (3 * S)] = v.y;
            s[(c4 * 4 + 2) * (3 * S)] = v.z;
            s[(c4 * 4 + 3) * (3 * S)] = v.w;
        }
        // stage weights for ALL 9 taps of this channel chunk: [pos][k][n]
        #pragma unroll 1
        for (int idx = tid; idx < 9 * BK * (BN / 4); idx += 256) {
            int n4  = idx % (BN / 4);
            int kk  = (idx / (BN / 4)) % BK;
            int pos = idx / (BN / 4) / BK;
            *(float4*)&sW[(pos * BK + kk) * BN + n4 * 4] =
                *(const float4*)(wg + ((size_t)pos * CIN + c0 + kk) * COUT + n4 * 4);
        }
        __syncthreads();

        #pragma unroll 1
        for (int k = 0; k < BK; k++) {
            const float* rowbase = sIn + k * (3 * S);
            #pragma unroll
            for (int ky = 0; ky < 3; ky++) {
                // 10-wide input window serves all 3 kx taps x 8 pixels
                const float* rp = rowbase + ky * S + ty * TM;
                ull aw[10];
                #pragma unroll
                for (int t = 0; t < 10; t++) aw[t] = pack2(rp[t]);
                #pragma unroll
                for (int kx = 0; kx < 3; kx++) {
                    const float* bp = &sW[((ky * 3 + kx) * BK + k) * BN + tx * TN];
                    ull b2[TN / 2];
                    #pragma unroll
                    for (int j = 0; j < TN / 2; j++) b2[j] = *(const ull*)(bp + 2 * j);
                    #pragma unroll
                    for (int i = 0; i < TM; i++) {
                        ull a = aw[i + kx];
                        #pragma unroll
                        for (int j = 0; j < TN / 2; j++) ffma2(acc[i][j], a, b2[j]);
                    }
                }
            }
        }
    }

    // epilogue: bias + leaky relu, float2 stores
    #pragma unroll
    for (int i = 0; i < TM; i++) {
        float* op = out + (size_t)(p0 + ty * TM + i) * COUT + tx * TN;
        #pragma unroll
        for (int j = 0; j < TN / 2; j++) {
            float2 v = unpack2(acc[i][j]);
            v.x += bias[tx * TN + 2 * j];
            v.y += bias[tx * TN + 2 * j + 1];
            if (LRELU) {
                v.x = (v.x >= 0.f) ? v.x : 0.2f * v.x;
                v.y = (v.y >= 0.f) ? v.y : 0.2f * v.y;
            }
            *(float2*)(op + 2 * j) = v;
        }
    }
}

// ---------------- final 32 -> 1 conv ----------------
__global__ void conv_last_kernel(const float* __restrict__ in, const float* __restrict__ k6,
                                 const float* __restrict__ b6, float* __restrict__ out)
{
    __shared__ float sw[288];
    int tid = threadIdx.x;
    for (int i = tid; i < 288; i += 256) sw[i] = k6[i];
    __syncthreads();

    int p = blockIdx.x * 256 + tid;
    int b = p >> 15, h = (p >> 8) & 127, w = p & 255;
    const float* inb = in + (size_t)(b * HH) * WW * 32;
    float acc = b6[0];
    #pragma unroll
    for (int ky = 0; ky < 3; ky++) {
        int hh = h + ky - 1;
        if ((unsigned)hh >= 128u) continue;
        #pragma unroll
        for (int kx = 0; kx < 3; kx++) {
            int ww = w + kx - 1;
            if ((unsigned)ww >= 256u) continue;
            const float4* ip = (const float4*)(inb + ((size_t)hh * 256 + ww) * 32);
            const float* wv = &sw[(ky * 3 + kx) * 32];
            #pragma unroll
            for (int q = 0; q < 8; q++) {
                float4 v = ip[q];
                acc += v.x * wv[4 * q + 0] + v.y * wv[4 * q + 1]
                     + v.z * wv[4 * q + 2] + v.w * wv[4 * q + 3];
            }
        }
    }
    out[p] = acc;
}

// ---------------- launch ----------------
template<int CIN, int COUT, int TN, bool LRELU>
static void launch_conv(const float* in, const float* w, const float* bias, float* out)
{
    constexpr int BK = 16, S = 132;
    int smemBytes = (BK * 3 * S + 9 * BK * COUT) * 4;
    cudaFuncSetAttribute((const void*)conv3x3_v2<CIN, COUT, TN, LRELU>,
                         cudaFuncAttributeMaxDynamicSharedMemorySize, smemBytes);
    conv3x3_v2<CIN, COUT, TN, LRELU><<<NP / 128, 256, smemBytes>>>(in, w, bias, out);
}

extern "C" void kernel_launch(void* const* d_in, const int* in_sizes, int n_in,
                              void* d_out, int out_size)
{
    (void)in_sizes; (void)n_in; (void)out_size;
    const float* left  = (const float*)d_in[0];
    const float* right = (const float*)d_in[1];
    const float* pd    = (const float*)d_in[2];
    const float* k1 = (const float*)d_in[3];  const float* b1 = (const float*)d_in[4];
    const float* k2 = (const float*)d_in[5];  const float* b2 = (const float*)d_in[6];
    const float* k3 = (const float*)d_in[7];  const float* b3 = (const float*)d_in[8];
    const float* k4 = (const float*)d_in[9];  const float* b4 = (const float*)d_in[10];
    const float* k5 = (const float*)d_in[11]; const float* b5 = (const float*)d_in[12];
    const float* k6 = (const float*)d_in[13]; const float* b6 = (const float*)d_in[14];
    float* out = (float*)d_out;

    float *vol, *bufA, *bufB, *w1;
    cudaGetSymbolAddress((void**)&vol,  g_vol);
    cudaGetSymbolAddress((void**)&bufA, g_bufA);
    cudaGetSymbolAddress((void**)&bufB, g_bufB);
    cudaGetSymbolAddress((void**)&w1,   g_w1);

    prep_kernel    <<<NP / 256, 256>>>(left, right, pd);
    buildvol_kernel<<<NP / 256, 256>>>(left);
    padw1_kernel   <<<(9 * CIN1P * 128 + 255) / 256, 256>>>(k1);

    launch_conv<CIN1P, 128, 8, true>(vol,  w1, b1, bufA);
    launch_conv<128,   128, 8, true>(bufA, k2, b2, bufB);
    launch_conv<128,    96, 6, true>(bufB, k3, b3, bufA);
    launch_conv<96,     64, 4, true>(bufA, k4, b4, bufB);
    launch_conv<64,     32, 2, true>(bufB, k5, b5, bufA);
    conv_last_kernel<<<NP / 256, 256>>>(bufA, k6, b6, out);
}

// round 5
// speedup vs baseline: 2.1475x; 1.5638x over previous
#include <cuda_runtime.h>
#include <cuda_bf16.h>
#include <cstdint>
#include <cstdio>

#define BB 8
#define HH 128
#define WW 256
#define CC 128
#define NP (BB*HH*WW)        // 262144 pixels

// ---------------- scratch (device globals; no allocations allowed) ----------------
__device__ __nv_bfloat16 g_actV[(size_t)NP * 320];   // layer1 input: hi(160)|lo(160)
__device__ __nv_bfloat16 g_actA[(size_t)NP * 256];   // ping
__device__ __nv_bfloat16 g_actB[(size_t)NP * 256];   // pong
__device__ float g_up  [NP];
__device__ float g_warp[NP];
__device__ float g_lm  [NP];
// split/transposed weights: [tap][chunk][n][ hi(32) | lo(32) ] bf16
__device__ __nv_bfloat16 g_wsp1[9 * 5 * 128 * 64];
__device__ __nv_bfloat16 g_wsp2[9 * 4 * 128 * 64];
__device__ __nv_bfloat16 g_wsp3[9 * 4 *  96 * 64];
__device__ __nv_bfloat16 g_wsp4[9 * 3 *  64 * 64];
__device__ __nv_bfloat16 g_wsp5[9 * 2 *  32 * 64];

// ---------------- PTX helpers ----------------
__device__ __forceinline__ uint32_t smem_u32(const void* p) {
    uint32_t a;
    asm("{ .reg .u64 t; cvta.to.shared.u64 t, %1; cvt.u32.u64 %0, t; }" : "=r"(a) : "l"(p));
    return a;
}
#define SWZ128(o) ((o) ^ (((o) >> 3) & 0x70))
#define CP16(dst, src, sz) asm volatile("cp.async.ca.shared.global [%0], [%1], 16, %2;" :: "r"(dst), "l"(src), "r"(sz))
#define CP_COMMIT()        asm volatile("cp.async.commit_group;" ::: "memory")
#define CP_WAIT()          asm volatile("cp.async.wait_group 0;" ::: "memory")

__device__ __forceinline__ void ldsm4(uint32_t r[4], uint32_t addr) {
    asm volatile("ldmatrix.sync.aligned.m8n8.x4.shared.b16 {%0,%1,%2,%3}, [%4];"
        : "=r"(r[0]), "=r"(r[1]), "=r"(r[2]), "=r"(r[3]) : "r"(addr));
}
__device__ __forceinline__ void mma16816(float* c, const uint32_t* a, uint32_t b0, uint32_t b1) {
    asm volatile("mma.sync.aligned.m16n8k16.row.col.f32.bf16.bf16.f32 "
        "{%0,%1,%2,%3}, {%4,%5,%6,%7}, {%8,%9}, {%0,%1,%2,%3};"
        : "+f"(c[0]), "+f"(c[1]), "+f"(c[2]), "+f"(c[3])
        : "r"(a[0]), "r"(a[1]), "r"(a[2]), "r"(a[3]), "r"(b0), "r"(b1));
}

// ---------------- prologue: upsample + warp + leftmean (fp32) ----------------
__global__ void prep_kernel(const float* __restrict__ left,
                            const float* __restrict__ right,
                            const float* __restrict__ pd)
{
    int p = blockIdx.x * 256 + threadIdx.x;
    int b = p >> 15;
    int h = (p >> 8) & 127;
    int w = p & 255;

    float sy = h * 0.5f - 0.25f;
    float fy = floorf(sy); float ty = sy - fy; int iy = (int)fy;
    int y0 = min(max(iy, 0), 63), y1 = min(max(iy + 1, 0), 63);
    float sx = w * 0.5f - 0.25f;
    float fx = floorf(sx); float tx = sx - fx; int ix = (int)fx;
    int x0 = min(max(ix, 0), 127), x1 = min(max(ix + 1, 0), 127);
    const float* q = pd + b * (64 * 128);
    float v00 = q[y0 * 128 + x0], v01 = q[y0 * 128 + x1];
    float v10 = q[y1 * 128 + x0], v11 = q[y1 * 128 + x1];
    float up = (1.f - ty) * ((1.f - tx) * v00 + tx * v01)
             + ty        * ((1.f - tx) * v10 + tx * v11);
    g_up[p] = up;

    float cx  = (float)w - up;
    float xf  = floorf(cx);
    float wt0 = (xf + 1.0f) - cx;
    float wt1 = cx - xf;
    float x0s = fminf(fmaxf(xf,       0.f), 255.f);
    float x1s = fminf(fmaxf(xf + 1.f, 0.f), 255.f);
    float basef = (float)(b * 32768) + (float)(h * 256);
    g_warp[p] = wt0 * right[(int)(x0s + basef)] + wt1 * right[(int)(x1s + basef)];

    const float4* lp = (const float4*)(left + (size_t)p * CC);
    float s = 0.f;
    #pragma unroll
    for (int q4 = 0; q4 < 32; q4++) { float4 v = lp[q4]; s += v.x + v.y + v.z + v.w; }
    g_lm[p] = s * (1.0f / 128.0f);
}

// ---------------- build split-bf16 144->160ch padded volume ----------------
__global__ void buildvol2(const float* __restrict__ left)
{
    int p = blockIdx.x * 256 + threadIdx.x;
    __nv_bfloat16* dst = g_actV + (size_t)p * 320;
    const float* src = left + (size_t)p * CC;
    #pragma unroll 4
    for (int c = 0; c < 128; c++) {
        float v = src[c];
        __nv_bfloat16 hi = __float2bfloat16(v);
        dst[c] = hi;
        dst[160 + c] = __float2bfloat16(v - __bfloat162float(hi));
    }
    float lm = g_lm[p];
    int w = p & 255;
    int prow = p & ~255;
    float ext[6];
    #pragma unroll
    for (int i = 0; i < 5; i++) {
        int ws = w + i - 2;
        ext[i] = ((unsigned)ws < 256u) ? lm * g_warp[prow + ws] : 0.f;
    }
    ext[5] = g_up[p];
    #pragma unroll
    for (int i = 0; i < 6; i++) {
        __nv_bfloat16 hi = __float2bfloat16(ext[i]);
        dst[128 + i] = hi;
        dst[160 + 128 + i] = __float2bfloat16(ext[i] - __bfloat162float(hi));
    }
    __nv_bfloat16 z = __float2bfloat16(0.f);
    #pragma unroll
    for (int i = 134; i < 160; i++) { dst[i] = z; dst[160 + i] = z; }
}

// ---------------- weight transpose + split: HWIO -> [tap][chunk][n][hi32|lo32] ----------------
__global__ void wsplit_kernel(const float* __restrict__ src, __nv_bfloat16* __restrict__ dst,
                              int CINlog, int COUT, int nch)
{
    int idx = blockIdx.x * 256 + threadIdx.x;
    int total = 9 * nch * COUT * 32;
    if (idx >= total) return;
    int kc = idx & 31;
    int n  = (idx >> 5) % COUT;
    int ch = ((idx >> 5) / COUT) % nch;
    int t  = (idx >> 5) / COUT / nch;
    int c  = ch * 32 + kc;
    float v = (c < CINlog) ? src[((size_t)t * CINlog + c) * COUT + n] : 0.f;
    __nv_bfloat16 hi = __float2bfloat16(v);
    __nv_bfloat16 lo = __float2bfloat16(v - __bfloat162float(hi));
    size_t base = (((size_t)t * nch + ch) * COUT + n) * 64;
    dst[base + kc] = hi;
    dst[base + 32 + kc] = lo;
}

// ---------------- HMMA conv layer ----------------
// CTA: 128 pixels (contiguous run in one image row) x COUT.
// 8 warps: warp w -> pixels (w&3)*32..+31 (2 m16 tiles), n-half (w>>2)*(COUT/2).
// Per (ky, chunk32): stage A halo tile (130 rows x 128B hi|lo, SW128) + W (3kx x COUT x 128B).
// 3-term bf16 split accumulated in fp32 registers via mma.sync m16n8k16.
template<int COUT, int NCH>
__global__ __launch_bounds__(256, 2)
void conv_mma(const __nv_bfloat16* __restrict__ act, const __nv_bfloat16* __restrict__ wsp,
              const float* __restrict__ bias, __nv_bfloat16* __restrict__ out)
{
    constexpr int CACT = NCH * 64;          // input pixel stride (bf16)
    constexpr int WT   = COUT * 128;        // bytes per W kx tile
    constexpr int NB8  = COUT / 16;         // n8 blocks per warp (half of COUT)
    extern __shared__ char smem[];
    const uint32_t sb    = smem_u32(smem);
    const uint32_t aBase = sb;              // 130 * 128B = 16640
    const uint32_t wBase = sb + 17408;      // 1024-aligned

    const int tid  = threadIdx.x;
    const int wz   = tid >> 5;
    const int lane = tid & 31;
    const int mw   = (wz & 3) * 32;         // warp pixel base
    const int nh   = (wz >> 2) * (COUT / 2);

    // ldmatrix lane address components
    const int a_row = lane & 15;
    const int a_kof = (lane >> 4) << 4;                    // 0 / 16 bytes
    const int b_n   = (lane & 7) | ((lane & 16) >> 1);
    const int b_kof = (lane & 8) << 1;                     // 0 / 16 bytes

    const int p0 = blockIdx.x * 128;
    const int b  = p0 >> 15;
    const int h  = (p0 >> 8) & 127;
    const int w0 = p0 & 255;

    float acc[2][NB8][4];
    #pragma unroll
    for (int mt = 0; mt < 2; mt++)
        #pragma unroll
        for (int j = 0; j < NB8; j++)
            #pragma unroll
            for (int q = 0; q < 4; q++) acc[mt][j][q] = 0.f;

    #pragma unroll 1
    for (int ky = 0; ky < 3; ky++) {
        const int hh = h + ky - 1;
        const bool rowok = (unsigned)hh < 128u;
        const int prow = (b << 15) + (hh << 8);
        #pragma unroll 1
        for (int ch = 0; ch < NCH; ch++) {
            __syncthreads();   // all warps done with previous tiles
            // ---- stage A: 130 halo rows x 8 x 16B (hi32|lo32 of this chunk)
            #pragma unroll 1
            for (int idx = tid; idx < 130 * 8; idx += 256) {
                int u = idx & 7;
                int r = idx >> 3;
                int ww = w0 + r - 1;
                bool ok = rowok && (unsigned)ww < 256u;
                size_t pix = ok ? (size_t)(prow + ww) : 0;
                int coff = (u < 4) ? (ch * 32 + u * 8)
                                   : (NCH * 32 + ch * 32 + (u - 4) * 8);
                const __nv_bfloat16* src = act + pix * CACT + coff;
                uint32_t dst = aBase + SWZ128(r * 128 + u * 16);
                CP16(dst, src, ok ? 16 : 0);
            }
            // ---- stage W: 3 kx tiles, COUT rows x 8 x 16B
            #pragma unroll 1
            for (int idx = tid; idx < 3 * COUT * 8; idx += 256) {
                int u  = idx & 7;
                int n  = (idx >> 3) % COUT;
                int kx = (idx >> 3) / COUT;
                const __nv_bfloat16* src =
                    wsp + (((size_t)(ky * 3 + kx) * NCH + ch) * COUT + n) * 64 + u * 8;
                uint32_t dst = wBase + kx * WT + SWZ128(n * 128 + u * 16);
                CP16(dst, src, 16);
            }
            CP_COMMIT();
            CP_WAIT();
            __syncthreads();

            #pragma unroll
            for (int kx = 0; kx < 3; kx++) {
                // A fragments: [mt][s]: s=0 hi.k0, 1 hi.k1, 2 lo.k0, 3 lo.k1
                uint32_t Af[2][4][4];
                #pragma unroll
                for (int mt = 0; mt < 2; mt++) {
                    int rbase = mw + mt * 16 + kx + a_row;
                    #pragma unroll
                    for (int s = 0; s < 4; s++)
                        ldsm4(Af[mt][s], aBase + SWZ128(rbase * 128 + s * 32 + a_kof));
                }
                #pragma unroll
                for (int nb = 0; nb < NB8 / 2; nb++) {
                    int nbase = nh + nb * 16 + b_n;
                    uint32_t wb = wBase + kx * WT;
                    uint32_t Bf[4][4];   // Whi0 Whi1 Wlo0 Wlo1 (each k16 x n16)
                    #pragma unroll
                    for (int s = 0; s < 4; s++)
                        ldsm4(Bf[s], wb + SWZ128(nbase * 128 + s * 32 + b_kof));
                    #pragma unroll
                    for (int mt = 0; mt < 2; mt++) {
                        float* c0 = acc[mt][2 * nb];
                        float* c1 = acc[mt][2 * nb + 1];
                        mma16816(c0, Af[mt][0], Bf[0][0], Bf[0][1]);  // Ahi0*Whi0
                        mma16816(c1, Af[mt][0], Bf[0][2], Bf[0][3]);
                        mma16816(c0, Af[mt][1], Bf[1][0], Bf[1][1]);  // Ahi1*Whi1
                        mma16816(c1, Af[mt][1], Bf[1][2], Bf[1][3]);
                        mma16816(c0, Af[mt][0], Bf[2][0], Bf[2][1]);  // Ahi0*Wlo0
                        mma16816(c1, Af[mt][0], Bf[2][2], Bf[2][3]);
                        mma16816(c0, Af[mt][1], Bf[3][0], Bf[3][1]);  // Ahi1*Wlo1
                        mma16816(c1, Af[mt][1], Bf[3][2], Bf[3][3]);
                        mma16816(c0, Af[mt][2], Bf[0][0], Bf[0][1]);  // Alo0*Whi0
                        mma16816(c1, Af[mt][2], Bf[0][2], Bf[0][3]);
                        mma16816(c0, Af[mt][3], Bf[1][0], Bf[1][1]);  // Alo1*Whi1
                        mma16816(c1, Af[mt][3], Bf[1][2], Bf[1][3]);
                    }
                }
            }
        }
    }

    // ---- epilogue: bias + lrelu + hi/lo split store
    const int mrow = lane >> 2;
    const int ncol = (lane & 3) * 2;
    #pragma unroll
    for (int mt = 0; mt < 2; mt++) {
        #pragma unroll
        for (int j = 0; j < NB8; j++) {
            int chn = nh + j * 8 + ncol;
            float bs0 = bias[chn], bs1 = bias[chn + 1];
            #pragma unroll
            for (int half = 0; half < 2; half++) {
                int p = p0 + mw + mt * 16 + mrow + half * 8;
                float y0 = acc[mt][j][2 * half + 0] + bs0;
                float y1 = acc[mt][j][2 * half + 1] + bs1;
                y0 = (y0 >= 0.f) ? y0 : 0.2f * y0;
                y1 = (y1 >= 0.f) ? y1 : 0.2f * y1;
                __nv_bfloat162 hp, lp;
                hp.x = __float2bfloat16(y0);
                hp.y = __float2bfloat16(y1);
                lp.x = __float2bfloat16(y0 - __bfloat162float(hp.x));
                lp.y = __float2bfloat16(y1 - __bfloat162float(hp.y));
                __nv_bfloat16* op = out + (size_t)p * (2 * COUT);
                *(uint32_t*)(op + chn)        = *(uint32_t*)&hp;
                *(uint32_t*)(op + COUT + chn) = *(uint32_t*)&lp;
            }
        }
    }
}

// ---------------- final 32 -> 1 conv (reads split-bf16 activations) ----------------
__global__ void conv_last2(const __nv_bfloat16* __restrict__ in, const float* __restrict__ k6,
                           const float* __restrict__ b6, float* __restrict__ out)
{
    __shared__ float sw[288];
    int tid = threadIdx.x;
    for (int i = tid; i < 288; i += 256) sw[i] = k6[i];
    __syncthreads();

    int p = blockIdx.x * 256 + tid;
    int b = p >> 15, h = (p >> 8) & 127, w = p & 255;
    const __nv_bfloat16* inb = in + (size_t)(b * HH) * WW * 64;
    float acc = b6[0];
    #pragma unroll
    for (int ky = 0; ky < 3; ky++) {
        int hh = h + ky - 1;
        if ((unsigned)hh >= 128u) continue;
        #pragma unroll
        for (int kx = 0; kx < 3; kx++) {
            int ww = w + kx - 1;
            if ((unsigned)ww >= 256u) continue;
            const __nv_bfloat16* ip = inb + ((size_t)hh * 256 + ww) * 64;
            const float* wv = &sw[(ky * 3 + kx) * 32];
            #pragma unroll
            for (int c = 0; c < 32; c++)
                acc += (__bfloat162float(ip[c]) + __bfloat162float(ip[32 + c])) * wv[c];
        }
    }
    out[p] = acc;
}

// ---------------- launch ----------------
template<int COUT, int NCH>
static void launch_mma(const __nv_bfloat16* act, const __nv_bfloat16* w,
                       const float* bias, __nv_bfloat16* out)
{
    int smemBytes = 17408 + 3 * COUT * 128;
    cudaFuncSetAttribute((const void*)conv_mma<COUT, NCH>,
                         cudaFuncAttributeMaxDynamicSharedMemorySize, smemBytes);
    conv_mma<COUT, NCH><<<NP / 128, 256, smemBytes>>>(act, w, bias, out);
}

extern "C" void kernel_launch(void* const* d_in, const int* in_sizes, int n_in,
                              void* d_out, int out_size)
{
    (void)in_sizes; (void)n_in; (void)out_size;
    const float* left  = (const float*)d_in[0];
    const float* right = (const float*)d_in[1];
    const float* pd    = (const float*)d_in[2];
    const float* k1 = (const float*)d_in[3];  const float* b1 = (const float*)d_in[4];
    const float* k2 = (const float*)d_in[5];  const float* b2 = (const float*)d_in[6];
    const float* k3 = (const float*)d_in[7];  const float* b3 = (const float*)d_in[8];
    const float* k4 = (const float*)d_in[9];  const float* b4 = (const float*)d_in[10];
    const float* k5 = (const float*)d_in[11]; const float* b5 = (const float*)d_in[12];
    const float* k6 = (const float*)d_in[13]; const float* b6 = (const float*)d_in[14];
    float* out = (float*)d_out;

    __nv_bfloat16 *actV, *actA, *actB, *w1, *w2, *w3, *w4, *w5;
    cudaGetSymbolAddress((void**)&actV, g_actV);
    cudaGetSymbolAddress((void**)&actA, g_actA);
    cudaGetSymbolAddress((void**)&actB, g_actB);
    cudaGetSymbolAddress((void**)&w1, g_wsp1);
    cudaGetSymbolAddress((void**)&w2, g_wsp2);
    cudaGetSymbolAddress((void**)&w3, g_wsp3);
    cudaGetSymbolAddress((void**)&w4, g_wsp4);
    cudaGetSymbolAddress((void**)&w5, g_wsp5);

    prep_kernel<<<NP / 256, 256>>>(left, right, pd);
    buildvol2  <<<NP / 256, 256>>>(left);
    wsplit_kernel<<<(9 * 5 * 128 * 32 + 255) / 256, 256>>>(k1, w1, 134, 128, 5);
    wsplit_kernel<<<(9 * 4 * 128 * 32 + 255) / 256, 256>>>(k2, w2, 128, 128, 4);
    wsplit_kernel<<<(9 * 4 *  96 * 32 + 255) / 256, 256>>>(k3, w3, 128,  96, 4);
    wsplit_kernel<<<(9 * 3 *  64 * 32 + 255) / 256, 256>>>(k4, w4,  96,  64, 3);
    wsplit_kernel<<<(9 * 2 *  32 * 32 + 255) / 256, 256>>>(k5, w5,  64,  32, 2);

    launch_mma<128, 5>(actV, w1, b1, actA);
    launch_mma<128, 4>(actA, w2, b2, actB);
    launch_mma< 96, 4>(actB, w3, b3, actA);
    launch_mma< 64, 3>(actA, w4, b4, actB);
    launch_mma< 32, 2>(actB, w5, b5, actA);
    conv_last2<<<NP / 256, 256>>>(actA, k6, b6, out);
}

// round 6
// speedup vs baseline: 2.8363x; 1.3208x over previous
#include <cuda_runtime.h>
#include <cuda_bf16.h>
#include <cstdint>
#include <cstdio>

#define BB 8
#define HH 128
#define WW 256
#define CC 128
#define NP (BB*HH*WW)        // 262144 pixels

// ---------------- scratch (device globals; no allocations allowed) ----------------
__device__ __nv_bfloat16 g_actV[(size_t)NP * 320];   // layer1 input: hi(160)|lo(160)
__device__ __nv_bfloat16 g_actA[(size_t)NP * 256];   // ping
__device__ __nv_bfloat16 g_actB[(size_t)NP * 256];   // pong
__device__ float g_up  [NP];
__device__ float g_warp[NP];
// split/transposed weights: [tap][chunk][n][ hi(32) | lo(32) ] bf16
__device__ __nv_bfloat16 g_wsp1[9 * 5 * 128 * 64];
__device__ __nv_bfloat16 g_wsp2[9 * 4 * 128 * 64];
__device__ __nv_bfloat16 g_wsp3[9 * 4 *  96 * 64];
__device__ __nv_bfloat16 g_wsp4[9 * 3 *  64 * 64];
__device__ __nv_bfloat16 g_wsp5[9 * 2 *  32 * 64];

// ---------------- PTX helpers ----------------
__device__ __forceinline__ uint32_t smem_u32(const void* p) {
    uint32_t a;
    asm("{ .reg .u64 t; cvta.to.shared.u64 t, %1; cvt.u32.u64 %0, t; }" : "=r"(a) : "l"(p));
    return a;
}
#define SWZ128(o) ((o) ^ (((o) >> 3) & 0x70))
#define CP16(dst, src, sz) asm volatile("cp.async.ca.shared.global [%0], [%1], 16, %2;" :: "r"(dst), "l"(src), "r"(sz))
#define CP_COMMIT()        asm volatile("cp.async.commit_group;" ::: "memory")
#define CP_WAIT0()         asm volatile("cp.async.wait_group 0;" ::: "memory")
#define CP_WAIT1()         asm volatile("cp.async.wait_group 1;" ::: "memory")

__device__ __forceinline__ void ldsm4(uint32_t r[4], uint32_t addr) {
    asm volatile("ldmatrix.sync.aligned.m8n8.x4.shared.b16 {%0,%1,%2,%3}, [%4];"
        : "=r"(r[0]), "=r"(r[1]), "=r"(r[2]), "=r"(r[3]) : "r"(addr));
}
__device__ __forceinline__ void mma16816(float* c, const uint32_t* a, uint32_t b0, uint32_t b1) {
    asm volatile("mma.sync.aligned.m16n8k16.row.col.f32.bf16.bf16.f32 "
        "{%0,%1,%2,%3}, {%4,%5,%6,%7}, {%8,%9}, {%0,%1,%2,%3};"
        : "+f"(c[0]), "+f"(c[1]), "+f"(c[2]), "+f"(c[3])
        : "r"(a[0]), "r"(a[1]), "r"(a[2]), "r"(a[3]), "r"(b0), "r"(b1));
}

// ---------------- prologue: upsample + warp (fp32) ----------------
__global__ void prep_kernel(const float* __restrict__ right,
                            const float* __restrict__ pd)
{
    int p = blockIdx.x * 256 + threadIdx.x;
    int b = p >> 15;
    int h = (p >> 8) & 127;
    int w = p & 255;

    float sy = h * 0.5f - 0.25f;
    float fy = floorf(sy); float ty = sy - fy; int iy = (int)fy;
    int y0 = min(max(iy, 0), 63), y1 = min(max(iy + 1, 0), 63);
    float sx = w * 0.5f - 0.25f;
    float fx = floorf(sx); float tx = sx - fx; int ix = (int)fx;
    int x0 = min(max(ix, 0), 127), x1 = min(max(ix + 1, 0), 127);
    const float* q = pd + b * (64 * 128);
    float v00 = q[y0 * 128 + x0], v01 = q[y0 * 128 + x1];
    float v10 = q[y1 * 128 + x0], v11 = q[y1 * 128 + x1];
    float up = (1.f - ty) * ((1.f - tx) * v00 + tx * v01)
             + ty        * ((1.f - tx) * v10 + tx * v11);
    g_up[p] = up;

    float cx  = (float)w - up;
    float xf  = floorf(cx);
    float wt0 = (xf + 1.0f) - cx;
    float wt1 = cx - xf;
    float x0s = fminf(fmaxf(xf,       0.f), 255.f);
    float x1s = fminf(fmaxf(xf + 1.f, 0.f), 255.f);
    float basef = (float)(b * 32768) + (float)(h * 256);
    g_warp[p] = wt0 * right[(int)(x0s + basef)] + wt1 * right[(int)(x1s + basef)];
}

// ---------------- build split-bf16 160ch padded volume (warp-cooperative) ----------------
__global__ void buildvol_w(const float* __restrict__ left)
{
    int wz   = threadIdx.x >> 5;
    int lane = threadIdx.x & 31;
    int pbase = blockIdx.x * 256 + wz * 32;
    #pragma unroll 1
    for (int i = 0; i < 32; i++) {
        int p = pbase + i;
        const float4* lp = (const float4*)(left + (size_t)p * CC);
        float4 v = lp[lane];                           // coalesced 512B per warp
        float t = v.x + v.y + v.z + v.w;
        #pragma unroll
        for (int m = 16; m > 0; m >>= 1) t += __shfl_xor_sync(0xffffffffu, t, m);
        float lm = t * (1.0f / 128.0f);

        __nv_bfloat16* dst = g_actV + (size_t)p * 320;
        __nv_bfloat16 ha[4], la[4];
        float vv[4] = {v.x, v.y, v.z, v.w};
        #pragma unroll
        for (int j = 0; j < 4; j++) {
            ha[j] = __float2bfloat16(vv[j]);
            la[j] = __float2bfloat16(vv[j] - __bfloat162float(ha[j]));
        }
        *(uint2*)(dst + lane * 4)       = *(uint2*)ha;   // coalesced
        *(uint2*)(dst + 160 + lane * 4) = *(uint2*)la;

        // ext channels 128..159: lanes 0-4 cost, 5 up, 6-31 zero pad
        int w = p & 255;
        int prow = p & ~255;
        float val = 0.f;
        if (lane < 5) {
            int ws = w + lane - 2;
            val = ((unsigned)ws < 256u) ? lm * g_warp[prow + ws] : 0.f;
        } else if (lane == 5) {
            val = g_up[p];
        }
        __nv_bfloat16 hi = __float2bfloat16(val);
        dst[128 + lane]       = hi;
        dst[160 + 128 + lane] = __float2bfloat16(val - __bfloat162float(hi));
    }
}

// ---------------- weight transpose + split: HWIO -> [tap][chunk][n][hi32|lo32] ----------------
__global__ void wsplit_kernel(const float* __restrict__ src, __nv_bfloat16* __restrict__ dst,
                              int CINlog, int COUT, int nch)
{
    int idx = blockIdx.x * 256 + threadIdx.x;
    int total = 9 * nch * COUT * 32;
    if (idx >= total) return;
    int kc = idx & 31;
    int n  = (idx >> 5) % COUT;
    int ch = ((idx >> 5) / COUT) % nch;
    int t  = (idx >> 5) / COUT / nch;
    int c  = ch * 32 + kc;
    float v = (c < CINlog) ? src[((size_t)t * CINlog + c) * COUT + n] : 0.f;
    __nv_bfloat16 hi = __float2bfloat16(v);
    __nv_bfloat16 lo = __float2bfloat16(v - __bfloat162float(hi));
    size_t base = (((size_t)t * nch + ch) * COUT + n) * 64;
    dst[base + kc] = hi;
    dst[base + 32 + kc] = lo;
}

// ---------------- HMMA conv layer, 2-stage cp.async pipeline ----------------
// CTA: 128 pixels x COUT. Warp w: pixels (w&3)*32..+31, n-half (w>>2)*(COUT/2).
// Per (ky,chunk): A halo tile 130x128B (hi32|lo32, SW128) + W (3kx x COUT x 128B).
// Double-buffered: stage it+1 while computing it.
template<int COUT, int NCH>
__global__ __launch_bounds__(256, 2)
void conv_mma(const __nv_bfloat16* __restrict__ act, const __nv_bfloat16* __restrict__ wsp,
              const float* __restrict__ bias, __nv_bfloat16* __restrict__ out)
{
    constexpr int CACT  = NCH * 64;
    constexpr int WT    = COUT * 128;
    constexpr int NB8   = COUT / 16;
    constexpr int STAGE = 17408 + 3 * WT;       // A area (16640 pad to 17408) + W
    constexpr int ITERS = 3 * NCH;
    extern __shared__ char smem[];
    const uint32_t sb = smem_u32(smem);

    const int tid  = threadIdx.x;
    const int wz   = tid >> 5;
    const int lane = tid & 31;
    const int mw   = (wz & 3) * 32;
    const int nh   = (wz >> 2) * (COUT / 2);

    const int a_row = lane & 15;
    const int a_kof = (lane >> 4) << 4;
    const int b_n   = (lane & 7) | ((lane & 16) >> 1);
    const int b_kof = (lane & 8) << 1;

    const int p0 = blockIdx.x * 128;
    const int b  = p0 >> 15;
    const int h  = (p0 >> 8) & 127;
    const int w0 = p0 & 255;

    float acc[2][NB8][4];
    #pragma unroll
    for (int mt = 0; mt < 2; mt++)
        #pragma unroll
        for (int j = 0; j < NB8; j++)
            #pragma unroll
            for (int q = 0; q < 4; q++) acc[mt][j][q] = 0.f;

    auto stage = [&](int it, int s) {
        int ky = it / NCH, ch = it % NCH;
        int hh = h + ky - 1;
        bool rowok = (unsigned)hh < 128u;
        int prow = (b << 15) + (hh << 8);
        uint32_t aB = sb + s * STAGE;
        uint32_t wB = aB + 17408;
        #pragma unroll 1
        for (int idx = tid; idx < 130 * 8; idx += 256) {
            int u = idx & 7;
            int r = idx >> 3;
            int ww = w0 + r - 1;
            bool ok = rowok && (unsigned)ww < 256u;
            size_t pix = ok ? (size_t)(prow + ww) : 0;
            int coff = (u < 4) ? (ch * 32 + u * 8)
                               : (NCH * 32 + ch * 32 + (u - 4) * 8);
            const __nv_bfloat16* src = act + pix * CACT + coff;
            CP16(aB + SWZ128(r * 128 + u * 16), src, ok ? 16 : 0);
        }
        #pragma unroll 1
        for (int idx = tid; idx < 3 * COUT * 8; idx += 256) {
            int u  = idx & 7;
            int n  = (idx >> 3) % COUT;
            int kx = (idx >> 3) / COUT;
            const __nv_bfloat16* src =
                wsp + (((size_t)(ky * 3 + kx) * NCH + ch) * COUT + n) * 64 + u * 8;
            CP16(wB + kx * WT + SWZ128(n * 128 + u * 16), src, 16);
        }
    };

    stage(0, 0);
    CP_COMMIT();

    #pragma unroll 1
    for (int it = 0; it < ITERS; it++) {
        const int s = it & 1;
        if (it + 1 < ITERS) {
            stage(it + 1, s ^ 1);
            CP_COMMIT();
            CP_WAIT1();          // current stage's group done; next in flight
        } else {
            CP_WAIT0();
        }
        __syncthreads();

        const uint32_t aBase = sb + s * STAGE;
        const uint32_t wBase = aBase + 17408;
        #pragma unroll
        for (int kx = 0; kx < 3; kx++) {
            uint32_t Af[2][4][4];   // [mt][hi.k0 hi.k1 lo.k0 lo.k1]
            #pragma unroll
            for (int mt = 0; mt < 2; mt++) {
                int rbase = mw + mt * 16 + kx + a_row;
                #pragma unroll
                for (int sfrag = 0; sfrag < 4; sfrag++)
                    ldsm4(Af[mt][sfrag], aBase + SWZ128(rbase * 128 + sfrag * 32 + a_kof));
            }
            #pragma unroll
            for (int nb = 0; nb < NB8 / 2; nb++) {
                int nbase = nh + nb * 16 + b_n;
                uint32_t wb = wBase + kx * WT;
                uint32_t Bf[4][4];   // Whi0 Whi1 Wlo0 Wlo1
                #pragma unroll
                for (int sfrag = 0; sfrag < 4; sfrag++)
                    ldsm4(Bf[sfrag], wb + SWZ128(nbase * 128 + sfrag * 32 + b_kof));
                #pragma unroll
                for (int mt = 0; mt < 2; mt++) {
                    float* c0 = acc[mt][2 * nb];
                    float* c1 = acc[mt][2 * nb + 1];
                    mma16816(c0, Af[mt][0], Bf[0][0], Bf[0][1]);  // Ahi0*Whi0
                    mma16816(c1, Af[mt][0], Bf[0][2], Bf[0][3]);
                    mma16816(c0, Af[mt][1], Bf[1][0], Bf[1][1]);  // Ahi1*Whi1
                    mma16816(c1, Af[mt][1], Bf[1][2], Bf[1][3]);
                    mma16816(c0, Af[mt][0], Bf[2][0], Bf[2][1]);  // Ahi0*Wlo0
                    mma16816(c1, Af[mt][0], Bf[2][2], Bf[2][3]);
                    mma16816(c0, Af[mt][1], Bf[3][0], Bf[3][1]);  // Ahi1*Wlo1
                    mma16816(c1, Af[mt][1], Bf[3][2], Bf[3][3]);
                    mma16816(c0, Af[mt][2], Bf[0][0], Bf[0][1]);  // Alo0*Whi0
                    mma16816(c1, Af[mt][2], Bf[0][2], Bf[0][3]);
                    mma16816(c0, Af[mt][3], Bf[1][0], Bf[1][1]);  // Alo1*Whi1
                    mma16816(c1, Af[mt][3], Bf[1][2], Bf[1][3]);
                }
            }
        }
        __syncthreads();   // all warps done with buffer s before it is restaged
    }

    // ---- epilogue: bias + lrelu + hi/lo split store
    const int mrow = lane >> 2;
    const int ncol = (lane & 3) * 2;
    #pragma unroll
    for (int mt = 0; mt < 2; mt++) {
        #pragma unroll
        for (int j = 0; j < NB8; j++) {
            int chn = nh + j * 8 + ncol;
            float bs0 = bias[chn], bs1 = bias[chn + 1];
            #pragma unroll
            for (int half = 0; half < 2; half++) {
                int p = p0 + mw + mt * 16 + mrow + half * 8;
                float y0 = acc[mt][j][2 * half + 0] + bs0;
                float y1 = acc[mt][j][2 * half + 1] + bs1;
                y0 = (y0 >= 0.f) ? y0 : 0.2f * y0;
                y1 = (y1 >= 0.f) ? y1 : 0.2f * y1;
                __nv_bfloat162 hp, lp;
                hp.x = __float2bfloat16(y0);
                hp.y = __float2bfloat16(y1);
                lp.x = __float2bfloat16(y0 - __bfloat162float(hp.x));
                lp.y = __float2bfloat16(y1 - __bfloat162float(hp.y));
                __nv_bfloat16* op = out + (size_t)p * (2 * COUT);
                *(uint32_t*)(op + chn)        = *(uint32_t*)&hp;
                *(uint32_t*)(op + COUT + chn) = *(uint32_t*)&lp;
            }
        }
    }
}

// ---------------- final 32 -> 1 conv (vectorized bf16 reads) ----------------
__global__ void conv_last2(const __nv_bfloat16* __restrict__ in, const float* __restrict__ k6,
                           const float* __restrict__ b6, float* __restrict__ out)
{
    __shared__ float sw[288];
    int tid = threadIdx.x;
    for (int i = tid; i < 288; i += 256) sw[i] = k6[i];
    __syncthreads();

    int p = blockIdx.x * 256 + tid;
    int b = p >> 15, h = (p >> 8) & 127, w = p & 255;
    const __nv_bfloat16* inb = in + (size_t)(b * HH) * WW * 64;
    float acc = b6[0];
    #pragma unroll
    for (int ky = 0; ky < 3; ky++) {
        int hh = h + ky - 1;
        if ((unsigned)hh >= 128u) continue;
        #pragma unroll
        for (int kx = 0; kx < 3; kx++) {
            int ww = w + kx - 1;
            if ((unsigned)ww >= 256u) continue;
            const __nv_bfloat16* ip = inb + ((size_t)hh * 256 + ww) * 64;
            const __nv_bfloat162* iph = (const __nv_bfloat162*)ip;
            const __nv_bfloat162* ipl = (const __nv_bfloat162*)(ip + 32);
            const float* wv = &sw[(ky * 3 + kx) * 32];
            #pragma unroll
            for (int c2 = 0; c2 < 16; c2++) {
                float2 hv = __bfloat1622float2(iph[c2]);
                float2 lv = __bfloat1622float2(ipl[c2]);
                acc += (hv.x + lv.x) * wv[2 * c2] + (hv.y + lv.y) * wv[2 * c2 + 1];
            }
        }
    }
    out[p] = acc;
}

// ---------------- launch ----------------
template<int COUT, int NCH>
static void launch_mma(const __nv_bfloat16* act, const __nv_bfloat16* w,
                       const float* bias, __nv_bfloat16* out)
{
    int smemBytes = 2 * (17408 + 3 * COUT * 128);
    cudaFuncSetAttribute((const void*)conv_mma<COUT, NCH>,
                         cudaFuncAttributeMaxDynamicSharedMemorySize, smemBytes);
    conv_mma<COUT, NCH><<<NP / 128, 256, smemBytes>>>(act, w, bias, out);
}

extern "C" void kernel_launch(void* const* d_in, const int* in_sizes, int n_in,
                              void* d_out, int out_size)
{
    (void)in_sizes; (void)n_in; (void)out_size;
    const float* left  = (const float*)d_in[0];
    const float* right = (const float*)d_in[1];
    const float* pd    = (const float*)d_in[2];
    const float* k1 = (const float*)d_in[3];  const float* b1 = (const float*)d_in[4];
    const float* k2 = (const float*)d_in[5];  const float* b2 = (const float*)d_in[6];
    const float* k3 = (const float*)d_in[7];  const float* b3 = (const float*)d_in[8];
    const float* k4 = (const float*)d_in[9];  const float* b4 = (const float*)d_in[10];
    const float* k5 = (const float*)d_in[11]; const float* b5 = (const float*)d_in[12];
    const float* k6 = (const float*)d_in[13]; const float* b6 = (const float*)d_in[14];
    float* out = (float*)d_out;

    __nv_bfloat16 *actV, *actA, *actB, *w1, *w2, *w3, *w4, *w5;
    cudaGetSymbolAddress((void**)&actV, g_actV);
    cudaGetSymbolAddress((void**)&actA, g_actA);
    cudaGetSymbolAddress((void**)&actB, g_actB);
    cudaGetSymbolAddress((void**)&w1, g_wsp1);
    cudaGetSymbolAddress((void**)&w2, g_wsp2);
    cudaGetSymbolAddress((void**)&w3, g_wsp3);
    cudaGetSymbolAddress((void**)&w4, g_wsp4);
    cudaGetSymbolAddress((void**)&w5, g_wsp5);

    // launch order arranged so ncu (-s 5 -c 1) profiles conv1 (6th launch)
    wsplit_kernel<<<(9 * 5 * 128 * 32 + 255) / 256, 256>>>(k1, w1, 134, 128, 5);  // 1
    wsplit_kernel<<<(9 * 4 * 128 * 32 + 255) / 256, 256>>>(k2, w2, 128, 128, 4);  // 2
    wsplit_kernel<<<(9 * 4 *  96 * 32 + 255) / 256, 256>>>(k3, w3, 128,  96, 4);  // 3
    prep_kernel<<<NP / 256, 256>>>(right, pd);                                     // 4
    buildvol_w <<<NP / 256, 256>>>(left);                                          // 5
    launch_mma<128, 5>(actV, w1, b1, actA);                                        // 6 <- profiled
    wsplit_kernel<<<(9 * 3 *  64 * 32 + 255) / 256, 256>>>(k4, w4,  96,  64, 3);   // 7
    wsplit_kernel<<<(9 * 2 *  32 * 32 + 255) / 256, 256>>>(k5, w5,  64,  32, 2);   // 8
    launch_mma<128, 4>(actA, w2, b2, actB);
    launch_mma< 96, 4>(actB, w3, b3, actA);
    launch_mma< 64, 3>(actA, w4, b4, actB);
    launch_mma< 32, 2>(actB, w5, b5, actA);
    conv_last2<<<NP / 256, 256>>>(actA, k6, b6, out);
}

// round 7
// speedup vs baseline: 4.0243x; 1.4189x over previous
#include <cuda_runtime.h>
#include <cuda_fp16.h>
#include <cstdint>
#include <cstdio>

#define BB 8
#define HH 128
#define WW 256
#define CC 128
#define NP (BB*HH*WW)        // 262144 pixels

// ---------------- scratch (device globals; no allocations allowed) ----------------
__device__ __half g_actV[(size_t)NP * 320];   // layer1 input: hi(160)|lo(160) fp16
__device__ __half g_actA[(size_t)NP * 256];   // ping
__device__ __half g_actB[(size_t)NP * 256];   // pong
__device__ float g_up  [NP];
__device__ float g_warp[NP];
// fp16 transposed weights: [tap][chunk][n][32] (hi only)
__device__ __half g_wsp1[9 * 5 * 128 * 32];
__device__ __half g_wsp2[9 * 4 * 128 * 32];
__device__ __half g_wsp3[9 * 4 *  96 * 32];
__device__ __half g_wsp4[9 * 3 *  64 * 32];
__device__ __half g_wsp5[9 * 2 *  32 * 32];

// ---------------- PTX helpers ----------------
__device__ __forceinline__ uint32_t smem_u32(const void* p) {
    uint32_t a;
    asm("{ .reg .u64 t; cvta.to.shared.u64 t, %1; cvt.u32.u64 %0, t; }" : "=r"(a) : "l"(p));
    return a;
}
#define SWZ128(o) ((o) ^ (((o) >> 3) & 0x70))
#define SWZ64(o)  ((o) ^ (((o) >> 3) & 0x30))
#define CP16(dst, src, sz) asm volatile("cp.async.ca.shared.global [%0], [%1], 16, %2;" :: "r"(dst), "l"(src), "r"(sz))
#define CP_COMMIT()        asm volatile("cp.async.commit_group;" ::: "memory")
#define CP_WAIT0()         asm volatile("cp.async.wait_group 0;" ::: "memory")
#define CP_WAIT1()         asm volatile("cp.async.wait_group 1;" ::: "memory")

__device__ __forceinline__ void ldsm4(uint32_t r[4], uint32_t addr) {
    asm volatile("ldmatrix.sync.aligned.m8n8.x4.shared.b16 {%0,%1,%2,%3}, [%4];"
        : "=r"(r[0]), "=r"(r[1]), "=r"(r[2]), "=r"(r[3]) : "r"(addr));
}
__device__ __forceinline__ void mma16816(float* c, const uint32_t* a, uint32_t b0, uint32_t b1) {
    asm volatile("mma.sync.aligned.m16n8k16.row.col.f32.f16.f16.f32 "
        "{%0,%1,%2,%3}, {%4,%5,%6,%7}, {%8,%9}, {%0,%1,%2,%3};"
        : "+f"(c[0]), "+f"(c[1]), "+f"(c[2]), "+f"(c[3])
        : "r"(a[0]), "r"(a[1]), "r"(a[2]), "r"(a[3]), "r"(b0), "r"(b1));
}

// ---------------- prologue: upsample + warp (fp32) ----------------
__global__ void prep_kernel(const float* __restrict__ right,
                            const float* __restrict__ pd)
{
    int p = blockIdx.x * 256 + threadIdx.x;
    int b = p >> 15;
    int h = (p >> 8) & 127;
    int w = p & 255;

    float sy = h * 0.5f - 0.25f;
    float fy = floorf(sy); float ty = sy - fy; int iy = (int)fy;
    int y0 = min(max(iy, 0), 63), y1 = min(max(iy + 1, 0), 63);
    float sx = w * 0.5f - 0.25f;
    float fx = floorf(sx); float tx = sx - fx; int ix = (int)fx;
    int x0 = min(max(ix, 0), 127), x1 = min(max(ix + 1, 0), 127);
    const float* q = pd + b * (64 * 128);
    float v00 = q[y0 * 128 + x0], v01 = q[y0 * 128 + x1];
    float v10 = q[y1 * 128 + x0], v11 = q[y1 * 128 + x1];
    float up = (1.f - ty) * ((1.f - tx) * v00 + tx * v01)
             + ty        * ((1.f - tx) * v10 + tx * v11);
    g_up[p] = up;

    float cx  = (float)w - up;
    float xf  = floorf(cx);
    float wt0 = (xf + 1.0f) - cx;
    float wt1 = cx - xf;
    float x0s = fminf(fmaxf(xf,       0.f), 255.f);
    float x1s = fminf(fmaxf(xf + 1.f, 0.f), 255.f);
    float basef = (float)(b * 32768) + (float)(h * 256);
    g_warp[p] = wt0 * right[(int)(x0s + basef)] + wt1 * right[(int)(x1s + basef)];
}

// ---------------- build split-fp16 160ch padded volume (warp-cooperative) ----------------
__global__ void buildvol_w(const float* __restrict__ left)
{
    int wz   = threadIdx.x >> 5;
    int lane = threadIdx.x & 31;
    int pbase = blockIdx.x * 256 + wz * 32;
    #pragma unroll 1
    for (int i = 0; i < 32; i++) {
        int p = pbase + i;
        const float4* lp = (const float4*)(left + (size_t)p * CC);
        float4 v = lp[lane];
        float t = v.x + v.y + v.z + v.w;
        #pragma unroll
        for (int m = 16; m > 0; m >>= 1) t += __shfl_xor_sync(0xffffffffu, t, m);
        float lm = t * (1.0f / 128.0f);

        __half* dst = g_actV + (size_t)p * 320;
        __half ha[4], la[4];
        float vv[4] = {v.x, v.y, v.z, v.w};
        #pragma unroll
        for (int j = 0; j < 4; j++) {
            ha[j] = __float2half_rn(vv[j]);
            la[j] = __float2half_rn(vv[j] - __half2float(ha[j]));
        }
        *(uint2*)(dst + lane * 4)       = *(uint2*)ha;
        *(uint2*)(dst + 160 + lane * 4) = *(uint2*)la;

        int w = p & 255;
        int prow = p & ~255;
        float val = 0.f;
        if (lane < 5) {
            int ws = w + lane - 2;
            val = ((unsigned)ws < 256u) ? lm * g_warp[prow + ws] : 0.f;
        } else if (lane == 5) {
            val = g_up[p];
        }
        __half hi = __float2half_rn(val);
        dst[128 + lane]       = hi;
        dst[160 + 128 + lane] = __float2half_rn(val - __half2float(hi));
    }
}

// ---------------- weight transpose to fp16: HWIO -> [tap][chunk][n][32] ----------------
__global__ void wsplit_kernel(const float* __restrict__ src, __half* __restrict__ dst,
                              int CINlog, int COUT, int nch)
{
    int idx = blockIdx.x * 256 + threadIdx.x;
    int total = 9 * nch * COUT * 32;
    if (idx >= total) return;
    int kc = idx & 31;
    int n  = (idx >> 5) % COUT;
    int ch = ((idx >> 5) / COUT) % nch;
    int t  = (idx >> 5) / COUT / nch;
    int c  = ch * 32 + kc;
    float v = (c < CINlog) ? src[((size_t)t * CINlog + c) * COUT + n] : 0.f;
    dst[(((size_t)t * nch + ch) * COUT + n) * 32 + kc] = __float2half_rn(v);
}

// ---------------- HMMA conv layer, 2-term fp16 split, 2-stage cp.async pipeline ----------------
// CTA: 128 pixels x COUT. Warp w: pixels (w&3)*32..+31, n-half (w>>2)*(COUT/2).
// Per (ky,chunk32): A halo tile 130x128B (Ahi32|Alo32 fp16, SW128) + W (3kx x COUT x 64B, SW64).
// D = Ahi*W + Alo*W accumulated in fp32 registers.
template<int COUT, int NCH>
__global__ __launch_bounds__(256, 2)
void conv_mma(const __half* __restrict__ act, const __half* __restrict__ wsp,
              const float* __restrict__ bias, __half* __restrict__ out)
{
    constexpr int CACT  = NCH * 64;
    constexpr int WT    = COUT * 64;             // bytes per W kx tile (64B rows, SW64)
    constexpr int NB8   = COUT / 16;
    constexpr int STAGE = 17408 + 3 * WT;
    constexpr int ITERS = 3 * NCH;
    extern __shared__ char smem[];
    const uint32_t sb = smem_u32(smem);

    const int tid  = threadIdx.x;
    const int wz   = tid >> 5;
    const int lane = tid & 31;
    const int mw   = (wz & 3) * 32;
    const int nh   = (wz >> 2) * (COUT / 2);

    const int a_row = lane & 15;
    const int a_kof = (lane >> 4) << 4;
    const int b_n   = (lane & 7) | ((lane & 16) >> 1);
    const int b_kof = (lane & 8) << 1;

    const int p0 = blockIdx.x * 128;
    const int b  = p0 >> 15;
    const int h  = (p0 >> 8) & 127;
    const int w0 = p0 & 255;

    float acc[2][NB8][4];
    #pragma unroll
    for (int mt = 0; mt < 2; mt++)
        #pragma unroll
        for (int j = 0; j < NB8; j++)
            #pragma unroll
            for (int q = 0; q < 4; q++) acc[mt][j][q] = 0.f;

    auto stage = [&](int it, int s) {
        int ky = it / NCH, ch = it % NCH;
        int hh = h + ky - 1;
        bool rowok = (unsigned)hh < 128u;
        int prow = (b << 15) + (hh << 8);
        uint32_t aB = sb + s * STAGE;
        uint32_t wB = aB + 17408;
        #pragma unroll 1
        for (int idx = tid; idx < 130 * 8; idx += 256) {
            int u = idx & 7;
            int r = idx >> 3;
            int ww = w0 + r - 1;
            bool ok = rowok && (unsigned)ww < 256u;
            size_t pix = ok ? (size_t)(prow + ww) : 0;
            int coff = (u < 4) ? (ch * 32 + u * 8)
                               : (NCH * 32 + ch * 32 + (u - 4) * 8);
            const __half* src = act + pix * CACT + coff;
            CP16(aB + SWZ128(r * 128 + u * 16), src, ok ? 16 : 0);
        }
        #pragma unroll 1
        for (int idx = tid; idx < 3 * COUT * 4; idx += 256) {
            int u  = idx & 3;
            int n  = (idx >> 2) % COUT;
            int kx = (idx >> 2) / COUT;
            const __half* src =
                wsp + (((size_t)(ky * 3 + kx) * NCH + ch) * COUT + n) * 32 + u * 8;
            CP16(wB + kx * WT + SWZ64(n * 64 + u * 16), src, 16);
        }
    };

    stage(0, 0);
    CP_COMMIT();

    #pragma unroll 1
    for (int it = 0; it < ITERS; it++) {
        const int s = it & 1;
        if (it + 1 < ITERS) {
            stage(it + 1, s ^ 1);
            CP_COMMIT();
            CP_WAIT1();
        } else {
            CP_WAIT0();
        }
        __syncthreads();

        const uint32_t aBase = sb + s * STAGE;
        const uint32_t wBase = aBase + 17408;
        #pragma unroll
        for (int kx = 0; kx < 3; kx++) {
            uint32_t Af[2][4][4];   // [mt][hi.k0 hi.k1 lo.k0 lo.k1]
            #pragma unroll
            for (int mt = 0; mt < 2; mt++) {
                int rbase = mw + mt * 16 + kx + a_row;
                #pragma unroll
                for (int sf = 0; sf < 4; sf++)
                    ldsm4(Af[mt][sf], aBase + SWZ128(rbase * 128 + sf * 32 + a_kof));
            }
            #pragma unroll
            for (int nb = 0; nb < NB8 / 2; nb++) {
                int nbase = nh + nb * 16 + b_n;
                uint32_t wb = wBase + kx * WT;
                uint32_t Bf[2][4];   // W k0, W k1 (each k16 x n16)
                #pragma unroll
                for (int sf = 0; sf < 2; sf++)
                    ldsm4(Bf[sf], wb + SWZ64(nbase * 64 + sf * 32 + b_kof));
                #pragma unroll
                for (int mt = 0; mt < 2; mt++) {
                    float* c0 = acc[mt][2 * nb];
                    float* c1 = acc[mt][2 * nb + 1];
                    mma16816(c0, Af[mt][0], Bf[0][0], Bf[0][1]);  // Ahi.k0 * W.k0
                    mma16816(c1, Af[mt][0], Bf[0][2], Bf[0][3]);
                    mma16816(c0, Af[mt][1], Bf[1][0], Bf[1][1]);  // Ahi.k1 * W.k1
                    mma16816(c1, Af[mt][1], Bf[1][2], Bf[1][3]);
                    mma16816(c0, Af[mt][2], Bf[0][0], Bf[0][1]);  // Alo.k0 * W.k0
                    mma16816(c1, Af[mt][2], Bf[0][2], Bf[0][3]);
                    mma16816(c0, Af[mt][3], Bf[1][0], Bf[1][1]);  // Alo.k1 * W.k1
                    mma16816(c1, Af[mt][3], Bf[1][2], Bf[1][3]);
                }
            }
        }
        __syncthreads();
    }

    // ---- epilogue: bias + lrelu + hi/lo fp16 split store
    const int mrow = lane >> 2;
    const int ncol = (lane & 3) * 2;
    #pragma unroll
    for (int mt = 0; mt < 2; mt++) {
        #pragma unroll
        for (int j = 0; j < NB8; j++) {
            int chn = nh + j * 8 + ncol;
            float bs0 = bias[chn], bs1 = bias[chn + 1];
            #pragma unroll
            for (int half = 0; half < 2; half++) {
                int p = p0 + mw + mt * 16 + mrow + half * 8;
                float y0 = acc[mt][j][2 * half + 0] + bs0;
                float y1 = acc[mt][j][2 * half + 1] + bs1;
                y0 = (y0 >= 0.f) ? y0 : 0.2f * y0;
                y1 = (y1 >= 0.f) ? y1 : 0.2f * y1;
                __half2 hp, lp;
                hp.x = __float2half_rn(y0);
                hp.y = __float2half_rn(y1);
                lp.x = __float2half_rn(y0 - __half2float(hp.x));
                lp.y = __float2half_rn(y1 - __half2float(hp.y));
                __half* op = out + (size_t)p * (2 * COUT);
                *(uint32_t*)(op + chn)        = *(uint32_t*)&hp;
                *(uint32_t*)(op + COUT + chn) = *(uint32_t*)&lp;
            }
        }
    }
}

// ---------------- final 32 -> 1 conv (fp16 hi+lo reads) ----------------
__global__ void conv_last2(const __half* __restrict__ in, const float* __restrict__ k6,
                           const float* __restrict__ b6, float* __restrict__ out)
{
    __shared__ float sw[288];
    int tid = threadIdx.x;
    for (int i = tid; i < 288; i += 256) sw[i] = k6[i];
    __syncthreads();

    int p = blockIdx.x * 256 + tid;
    int b = p >> 15, h = (p >> 8) & 127, w = p & 255;
    const __half* inb = in + (size_t)(b * HH) * WW * 64;
    float acc = b6[0];
    #pragma unroll
    for (int ky = 0; ky < 3; ky++) {
        int hh = h + ky - 1;
        if ((unsigned)hh >= 128u) continue;
        #pragma unroll
        for (int kx = 0; kx < 3; kx++) {
            int ww = w + kx - 1;
            if ((unsigned)ww >= 256u) continue;
            const __half* ip = inb + ((size_t)hh * 256 + ww) * 64;
            const __half2* iph = (const __half2*)ip;
            const __half2* ipl = (const __half2*)(ip + 32);
            const float* wv = &sw[(ky * 3 + kx) * 32];
            #pragma unroll
            for (int c2 = 0; c2 < 16; c2++) {
                float2 hv = __half22float2(iph[c2]);
                float2 lv = __half22float2(ipl[c2]);
                acc += (hv.x + lv.x) * wv[2 * c2] + (hv.y + lv.y) * wv[2 * c2 + 1];
            }
        }
    }
    out[p] = acc;
}

// ---------------- launch ----------------
template<int COUT, int NCH>
static void launch_mma(const __half* act, const __half* w,
                       const float* bias, __half* out)
{
    int smemBytes = 2 * (17408 + 3 * COUT * 64);
    cudaFuncSetAttribute((const void*)conv_mma<COUT, NCH>,
                         cudaFuncAttributeMaxDynamicSharedMemorySize, smemBytes);
    conv_mma<COUT, NCH><<<NP / 128, 256, smemBytes>>>(act, w, bias, out);
}

extern "C" void kernel_launch(void* const* d_in, const int* in_sizes, int n_in,
                              void* d_out, int out_size)
{
    (void)in_sizes; (void)n_in; (void)out_size;
    const float* left  = (const float*)d_in[0];
    const float* right = (const float*)d_in[1];
    const float* pd    = (const float*)d_in[2];
    const float* k1 = (const float*)d_in[3];  const float* b1 = (const float*)d_in[4];
    const float* k2 = (const float*)d_in[5];  const float* b2 = (const float*)d_in[6];
    const float* k3 = (const float*)d_in[7];  const float* b3 = (const float*)d_in[8];
    const float* k4 = (const float*)d_in[9];  const float* b4 = (const float*)d_in[10];
    const float* k5 = (const float*)d_in[11]; const float* b5 = (const float*)d_in[12];
    const float* k6 = (const float*)d_in[13]; const float* b6 = (const float*)d_in[14];
    float* out = (float*)d_out;

    __half *actV, *actA, *actB, *w1, *w2, *w3, *w4, *w5;
    cudaGetSymbolAddress((void**)&actV, g_actV);
    cudaGetSymbolAddress((void**)&actA, g_actA);
    cudaGetSymbolAddress((void**)&actB, g_actB);
    cudaGetSymbolAddress((void**)&w1, g_wsp1);
    cudaGetSymbolAddress((void**)&w2, g_wsp2);
    cudaGetSymbolAddress((void**)&w3, g_wsp3);
    cudaGetSymbolAddress((void**)&w4, g_wsp4);
    cudaGetSymbolAddress((void**)&w5, g_wsp5);

    // profiled slot is empirically the 4th launch -> conv1 there
    wsplit_kernel<<<(9 * 5 * 128 * 32 + 255) / 256, 256>>>(k1, w1, 134, 128, 5);  // 1
    prep_kernel<<<NP / 256, 256>>>(right, pd);                                     // 2
    buildvol_w <<<NP / 256, 256>>>(left);                                          // 3
    launch_mma<128, 5>(actV, w1, b1, actA);                                        // 4 <- profiled
    wsplit_kernel<<<(9 * 4 * 128 * 32 + 255) / 256, 256>>>(k2, w2, 128, 128, 4);
    wsplit_kernel<<<(9 * 4 *  96 * 32 + 255) / 256, 256>>>(k3, w3, 128,  96, 4);
    wsplit_kernel<<<(9 * 3 *  64 * 32 + 255) / 256, 256>>>(k4, w4,  96,  64, 3);
    wsplit_kernel<<<(9 * 2 *  32 * 32 + 255) / 256, 256>>>(k5, w5,  64,  32, 2);
    launch_mma<128, 4>(actA, w2, b2, actB);
    launch_mma< 96, 4>(actB, w3, b3, actA);
    launch_mma< 64, 3>(actA, w4, b4, actB);
    launch_mma< 32, 2>(actB, w5, b5, actA);
    conv_last2<<<NP / 256, 256>>>(actA, k6, b6, out);
}